// round 15
// baseline (speedup 1.0000x reference)
#include <cuda_runtime.h>
#include <cuda_bf16.h>
#include <cstdint>

constexpr int B = 2, C = 2, D = 160, H = 192, W = 224;
constexpr int HW  = H * W;          // 43008
constexpr int DHW = D * H * W;      // 6,881,280

__device__ __forceinline__ float lerpf(float a, float b, float t) {
    return fmaf(t, b - a, a);
}

// Guaranteed-predicated global load: returns *p when cond!=0, else fallback.
// Emits @p LDG (dest preserved when predicated off) — never LDG+SEL.
__device__ __forceinline__ float ldg_if(const float* p, unsigned cond, float fallback) {
    float v = fallback;
    asm volatile("{\n\t"
                 ".reg .pred p0;\n\t"
                 "setp.ne.u32 p0, %1, 0;\n\t"
                 "@p0 ld.global.nc.f32 %0, [%2];\n\t"
                 "}"
                 : "+f"(v) : "r"(cond), "l"(p));
    return v;
}

// trilinear from taps t[z][y][x] laid out as t00x..t11y
__device__ __forceinline__ float tri(float t00x, float t00y, float t01x, float t01y,
                                     float t10x, float t10y, float t11x, float t11y,
                                     float fx, float fy, float fz) {
    float l0 = lerpf(lerpf(t00x, t00y, fx), lerpf(t01x, t01y, fx), fy);
    float l1 = lerpf(lerpf(t10x, t10y, fx), lerpf(t11x, t11y, fx), fy);
    return lerpf(l0, l1, fz);
}

__global__ __launch_bounds__(224, 7)
void affine_grid_sample_kernel(const float* __restrict__ src,
                               const float* __restrict__ mat,
                               float* __restrict__ out)
{
    const int w  = threadIdx.x;          // 0..W-1
    const int h0 = blockIdx.y * 2;       // even h; thread does h0, h0+1
    const int zz = blockIdx.z;           // 0..B*(D/2)-1
    const int b  = (zz >= D / 2) ? 1 : 0;
    const int d0 = 2 * (zz - (b ? D / 2 : 0));  // even d; thread does d0, d0+1

    const float4* m4 = (const float4*)(mat + b * 12);
    const float4 r0 = __ldg(m4 + 0);
    const float4 r1 = __ldg(m4 + 1);
    const float4 r2 = __ldg(m4 + 2);

    // base voxel A = (d0, h0, w)
    const float x = fmaf((float)w,  2.0f / (W - 1), -1.0f);
    const float y = fmaf((float)h0, 2.0f / (H - 1), -1.0f);
    const float z = fmaf((float)d0, 2.0f / (D - 1), -1.0f);

    const float gx = fmaf(r0.x, x, fmaf(r0.y, y, fmaf(r0.z, z, r0.w * (1.0f / D))));
    const float gy = fmaf(r1.x, x, fmaf(r1.y, y, fmaf(r1.z, z, r1.w * (1.0f / H))));
    const float gz = fmaf(r2.x, x, fmaf(r2.y, y, fmaf(r2.z, z, r2.w * (1.0f / W))));

    const float sW = 0.5f * (W - 1), sH = 0.5f * (H - 1), sD = 0.5f * (D - 1);
    const float ixA = (gx + 1.0f) * sW;
    const float iyA = (gy + 1.0f) * sH;
    const float izA = (gz + 1.0f) * sD;

    // one-step deltas along d and along h
    const float ddd = 2.0f / (D - 1), ddh = 2.0f / (H - 1);
    const float dxd = r0.z * (ddd * sW), dyd = r1.z * (ddd * sH), dzd = r2.z * (ddd * sD);
    const float dxh = r0.y * (ddh * sW), dyh = r1.y * (ddh * sH), dzh = r2.y * (ddh * sD);

    const float ixC = ixA + dxh, iyC = iyA + dyh, izC = izA + dzh;   // (d0, h0+1)
    const float ixB = ixA + dxd, iyB = iyA + dyd, izB = izA + dzd;   // (d0+1, h0)
    const float ixD = ixB + dxh, iyD = iyB + dyh, izD = izB + dzh;   // (d0+1, h0+1)

    const float flxA = floorf(ixA), flyA = floorf(iyA), flzA = floorf(izA);
    const float flxC = floorf(ixC), flyC = floorf(iyC), flzC = floorf(izC);
    const float flxB = floorf(ixB), flyB = floorf(iyB), flzB = floorf(izB);
    const float flxD = floorf(ixD), flyD = floorf(iyD), flzD = floorf(izD);

    const float fxA = ixA - flxA, fyA = iyA - flyA, fzA = izA - flzA;
    const float fxC = ixC - flxC, fyC = iyC - flyC, fzC = izC - flzC;
    const float fxB = ixB - flxB, fyB = iyB - flyB, fzB = izB - flzB;
    const float fxD = ixD - flxD, fyD = iyD - flyD, fzD = izD - flzD;

    const int xA0 = (int)flxA, yA0 = (int)flyA, zA0 = (int)flzA;
    const int xC0 = (int)flxC, yC0 = (int)flyC, zC0 = (int)flzC;
    const int xB0 = (int)flxB, yB0 = (int)flyB, zB0 = (int)flzB;
    const int xD0 = (int)flxD, yD0 = (int)flyD, zD0 = (int)flzD;

    // share predicates (fixups fire when !share)
    const unsigned nC  = !((xC0 == xA0) & (yC0 == yA0 + 1) & (zC0 == zA0));
    const unsigned nB  = !((xB0 == xA0) & (yB0 == yA0)     & (zB0 == zA0 + 1));
    const unsigned nDA = !((xD0 == xA0) & (yD0 == yA0 + 1) & (zD0 == zA0 + 1));
    const unsigned nDC = !((xD0 == xC0) & (yD0 == yC0)     & (zD0 == zC0 + 1));
    const unsigned nDB = !((xD0 == xB0) & (yD0 == yB0 + 1) & (zD0 == zB0));

    const int linA = (zA0 * H + yA0) * W + xA0;
    const int linC = (zC0 * H + yC0) * W + xC0;
    const int linB = (zB0 * H + yB0) * W + xB0;
    const int linD = (zD0 * H + yD0) * W + xD0;

    const bool interior =
        ((unsigned)xA0 < (unsigned)(W-1)) & ((unsigned)yA0 < (unsigned)(H-1)) & ((unsigned)zA0 < (unsigned)(D-1)) &
        ((unsigned)xC0 < (unsigned)(W-1)) & ((unsigned)yC0 < (unsigned)(H-1)) & ((unsigned)zC0 < (unsigned)(D-1)) &
        ((unsigned)xB0 < (unsigned)(W-1)) & ((unsigned)yB0 < (unsigned)(H-1)) & ((unsigned)zB0 < (unsigned)(D-1)) &
        ((unsigned)xD0 < (unsigned)(W-1)) & ((unsigned)yD0 < (unsigned)(H-1)) & ((unsigned)zD0 < (unsigned)(D-1));

    const float* sb = src + (size_t)b * (size_t)(C * DHW);
    const size_t ob = (size_t)b * (size_t)(C * DHW) + (size_t)((d0 * H + h0) * W + w);

    if (interior) {
#pragma unroll
        for (int ch = 0; ch < 2; ++ch) {
            const float* base = sb + (size_t)ch * DHW;
            float* o = out + (size_t)ch * DHW + ob;

            // ---- voxel A: full 8 taps ----
            const float* pA = base + linA;
            float a00x = __ldg(pA),          a00y = __ldg(pA + 1);
            float a01x = __ldg(pA + W),      a01y = __ldg(pA + W + 1);
            float a10x = __ldg(pA + HW),     a10y = __ldg(pA + HW + 1);
            float a11x = __ldg(pA + HW + W), a11y = __ldg(pA + HW + W + 1);
            o[0] = tri(a00x, a00y, a01x, a01y, a10x, a10y, a11x, a11y, fxA, fyA, fzA);

            // ---- voxel C (h+1): borrows its y-near rows from A ----
            const float* pC = base + linC;
            float c01x = __ldg(pC + W),      c01y = __ldg(pC + W + 1);       // (zC0,   yC0+1)
            float c11x = __ldg(pC + HW + W), c11y = __ldg(pC + HW + W + 1);  // (zC0+1, yC0+1)
            float c00x = ldg_if(pC,          nC, a01x), c00y = ldg_if(pC + 1,      nC, a01y);
            float c10x = ldg_if(pC + HW,     nC, a11x), c10y = ldg_if(pC + HW + 1, nC, a11y);
            o[W] = tri(c00x, c00y, c01x, c01y, c10x, c10y, c11x, c11y, fxC, fyC, fzC);

            // ---- voxel B (d+1): borrows its z-near plane from A ----
            const float* pB = base + linB;
            float b10x = __ldg(pB + HW),     b10y = __ldg(pB + HW + 1);      // (zB0+1, yB0)
            float b11x = __ldg(pB + HW + W), b11y = __ldg(pB + HW + W + 1);  // (zB0+1, yB0+1)
            float b00x = ldg_if(pB,          nB, a10x), b00y = ldg_if(pB + 1,     nB, a10y);
            float b01x = ldg_if(pB + W,      nB, a11x), b01y = ldg_if(pB + W + 1, nB, a11y);
            o[HW] = tri(b00x, b00y, b01x, b01y, b10x, b10y, b11x, b11y, fxB, fyB, fzB);

            // ---- voxel D (d+1,h+1): borrows from A, C, B; loads only far-far row ----
            const float* pD = base + linD;
            float d11x = __ldg(pD + HW + W), d11y = __ldg(pD + HW + W + 1);  // (zD0+1, yD0+1)
            float d00x = ldg_if(pD,          nDA, a11x), d00y = ldg_if(pD + 1,      nDA, a11y);
            float d01x = ldg_if(pD + W,      nDC, c11x), d01y = ldg_if(pD + W + 1,  nDC, c11y);
            float d10x = ldg_if(pD + HW,     nDB, b11x), d10y = ldg_if(pD + HW + 1, nDB, b11y);
            o[HW + W] = tri(d00x, d00y, d01x, d01y, d10x, d10y, d11x, d11y, fxD, fyD, fzD);

            // keep channel 1's loads out of channel 0's register window
            asm volatile("" ::: "memory");
        }
        return;
    }

    // ======== border path: per-voxel fully predicated, zero padding ========
#pragma unroll
    for (int v = 0; v < 4; ++v) {
        const int dh = v & 1, dd = v >> 1;
        const int x0 = (dd ? (dh ? xD0 : xB0) : (dh ? xC0 : xA0));
        const int y0 = (dd ? (dh ? yD0 : yB0) : (dh ? yC0 : yA0));
        const int z0 = (dd ? (dh ? zD0 : zB0) : (dh ? zC0 : zA0));
        const float fx = (dd ? (dh ? fxD : fxB) : (dh ? fxC : fxA));
        const float fy = (dd ? (dh ? fyD : fyB) : (dh ? fyC : fyA));
        const float fz = (dd ? (dh ? fzD : fzB) : (dh ? fzC : fzA));

        const bool vx0 = (unsigned)x0       < (unsigned)W;
        const bool vx1 = (unsigned)(x0 + 1) < (unsigned)W;
        const bool vy0 = (unsigned)y0       < (unsigned)H;
        const bool vy1 = (unsigned)(y0 + 1) < (unsigned)H;
        const bool vz0 = (unsigned)z0       < (unsigned)D;
        const bool vz1 = (unsigned)(z0 + 1) < (unsigned)D;

        const bool p000 = vz0 & vy0 & vx0, p001 = vz0 & vy0 & vx1;
        const bool p010 = vz0 & vy1 & vx0, p011 = vz0 & vy1 & vx1;
        const bool p100 = vz1 & vy0 & vx0, p101 = vz1 & vy0 & vx1;
        const bool p110 = vz1 & vy1 & vx0, p111 = vz1 & vy1 & vx1;

        const float* pbase = sb + ((size_t)((z0 * H + y0) * W + x0));
        const size_t oo = ob + (size_t)dd * HW + (size_t)dh * W;

#pragma unroll
        for (int ch = 0; ch < 2; ++ch) {
            const float* p = pbase + (size_t)ch * DHW;

            float t000 = p000 ? __ldg(p)              : 0.0f;
            float t001 = p001 ? __ldg(p + 1)          : 0.0f;
            float t010 = p010 ? __ldg(p + W)          : 0.0f;
            float t011 = p011 ? __ldg(p + W + 1)      : 0.0f;
            float t100 = p100 ? __ldg(p + HW)         : 0.0f;
            float t101 = p101 ? __ldg(p + HW + 1)     : 0.0f;
            float t110 = p110 ? __ldg(p + HW + W)     : 0.0f;
            float t111 = p111 ? __ldg(p + HW + W + 1) : 0.0f;

            out[oo + (size_t)ch * DHW] =
                tri(t000, t001, t010, t011, t100, t101, t110, t111, fx, fy, fz);
        }
    }
}

extern "C" void kernel_launch(void* const* d_in, const int* in_sizes, int n_in,
                              void* d_out, int out_size)
{
    const float* src = (const float*)d_in[0];
    const float* mat = (const float*)d_in[1];
    float* out = (float*)d_out;

    dim3 block(W, 1, 1);                  // 224 threads = 7 warps
    dim3 grid(1, H / 2, B * (D / 2));     // (1, 96, 160)
    affine_grid_sample_kernel<<<grid, block>>>(src, mat, out);
}

// round 16
// speedup vs baseline: 1.0831x; 1.0831x over previous
#include <cuda_runtime.h>
#include <cuda_bf16.h>
#include <cstdint>

constexpr int B = 2, C = 2, D = 160, H = 192, W = 224;
constexpr int HW  = H * W;          // 43008
constexpr int DHW = D * H * W;      // 6,881,280
constexpr int VPT = 4;              // z-chain length per thread

__device__ __forceinline__ float lerpf(float a, float b, float t) {
    return fmaf(t, b - a, a);
}

// Guaranteed-predicated global load: returns *p when cond!=0, else fallback.
// Emits @p LDG (dest preserved when predicated off) — never LDG+SEL.
__device__ __forceinline__ float ldg_if(const float* p, unsigned cond, float fallback) {
    float v = fallback;
    asm volatile("{\n\t"
                 ".reg .pred p0;\n\t"
                 "setp.ne.u32 p0, %1, 0;\n\t"
                 "@p0 ld.global.nc.f32 %0, [%2];\n\t"
                 "}"
                 : "+f"(v) : "r"(cond), "l"(p));
    return v;
}

__device__ __forceinline__ float tri(float l00, float l01, float l10, float l11,
                                     float u00, float u01, float u10, float u11,
                                     float fx, float fy, float fz) {
    float m0 = lerpf(lerpf(l00, l01, fx), lerpf(l10, l11, fx), fy);
    float m1 = lerpf(lerpf(u00, u01, fx), lerpf(u10, u11, fx), fy);
    return lerpf(m0, m1, fz);
}

__global__ __launch_bounds__(224, 6)
void affine_grid_sample_kernel(const float* __restrict__ src,
                               const float* __restrict__ mat,
                               float* __restrict__ out)
{
    const int w  = threadIdx.x;      // 0..W-1
    const int h  = blockIdx.y;       // 0..H-1
    const int zz = blockIdx.z;       // 0..B*(D/VPT)-1
    const int b  = (zz >= D / VPT) ? 1 : 0;
    const int d0 = VPT * (zz - (b ? D / VPT : 0));

    const float4* m4 = (const float4*)(mat + b * 12);
    const float4 r0 = __ldg(m4 + 0);
    const float4 r1 = __ldg(m4 + 1);
    const float4 r2 = __ldg(m4 + 2);

    const float x = fmaf((float)w,  2.0f / (W - 1), -1.0f);
    const float y = fmaf((float)h,  2.0f / (H - 1), -1.0f);
    const float z = fmaf((float)d0, 2.0f / (D - 1), -1.0f);

    const float gx = fmaf(r0.x, x, fmaf(r0.y, y, fmaf(r0.z, z, r0.w * (1.0f / D))));
    const float gy = fmaf(r1.x, x, fmaf(r1.y, y, fmaf(r1.z, z, r1.w * (1.0f / H))));
    const float gz = fmaf(r2.x, x, fmaf(r2.y, y, fmaf(r2.z, z, r2.w * (1.0f / W))));

    const float sW = 0.5f * (W - 1), sH = 0.5f * (H - 1), sD = 0.5f * (D - 1);
    const float ix0 = (gx + 1.0f) * sW;
    const float iy0 = (gy + 1.0f) * sH;
    const float iz0 = (gz + 1.0f) * sD;

    const float ddz = 2.0f / (D - 1);
    const float dix = r0.z * (ddz * sW);
    const float diy = r1.z * (ddz * sH);
    const float diz = r2.z * (ddz * sD);

    // per-voxel coords, fracs, offsets, share predicates — computed up front
    int  lin[VPT];
    float fx[VPT], fy[VPT], fz[VPT];
    unsigned need[VPT];          // need[v]: v's lower plane != (v-1)'s upper plane
    bool interior = true;
    int pxx = 0, pyy = 0, pzz_ = 0;

#pragma unroll
    for (int v = 0; v < VPT; ++v) {
        const float ix = fmaf((float)v, dix, ix0);
        const float iy = fmaf((float)v, diy, iy0);
        const float iz = fmaf((float)v, diz, iz0);
        const float flx = floorf(ix), fly = floorf(iy), flz = floorf(iz);
        fx[v] = ix - flx; fy[v] = iy - fly; fz[v] = iz - flz;
        const int x0 = (int)flx, y0 = (int)fly, z0 = (int)flz;
        lin[v] = (z0 * H + y0) * W + x0;
        interior &= ((unsigned)x0 < (unsigned)(W - 1)) &
                    ((unsigned)y0 < (unsigned)(H - 1)) &
                    ((unsigned)z0 < (unsigned)(D - 1));
        need[v] = (v == 0) ? 1u
                : (unsigned)(!((z0 == pzz_ + 1) & (y0 == pyy) & (x0 == pxx)));
        pxx = x0; pyy = y0; pzz_ = z0;
    }

    const float* sb = src + (size_t)b * (size_t)(C * DHW);
    const size_t ob = (size_t)b * (size_t)(C * DHW) + (size_t)((d0 * H + h) * W + w);

    if (interior) {
        // ===== fast path: chain-shared lower planes, @p-predicated fixups =====
#pragma unroll
        for (int ch = 0; ch < 2; ++ch) {
            const float* base = sb + (size_t)ch * DHW;
            float* o = out + (size_t)ch * DHW + ob;

            float cu00 = 0.f, cu01 = 0.f, cu10 = 0.f, cu11 = 0.f; // carried upper plane

#pragma unroll
            for (int v = 0; v < VPT; ++v) {
                const float* p = base + lin[v];

                // upper plane: always loaded
                const float u00 = __ldg(p + HW);
                const float u01 = __ldg(p + HW + 1);
                const float u10 = __ldg(p + HW + W);
                const float u11 = __ldg(p + HW + W + 1);

                float l00, l01, l10, l11;
                if (v == 0) {
                    l00 = __ldg(p);
                    l01 = __ldg(p + 1);
                    l10 = __ldg(p + W);
                    l11 = __ldg(p + W + 1);
                } else {
                    // true @p loads; fall back to carried plane (~81% of lanes)
                    l00 = ldg_if(p,         need[v], cu00);
                    l01 = ldg_if(p + 1,     need[v], cu01);
                    l10 = ldg_if(p + W,     need[v], cu10);
                    l11 = ldg_if(p + W + 1, need[v], cu11);
                }

                o[(size_t)v * HW] = tri(l00, l01, l10, l11,
                                        u00, u01, u10, u11,
                                        fx[v], fy[v], fz[v]);

                cu00 = u00; cu01 = u01; cu10 = u10; cu11 = u11;
            }

            // keep channel 1's loads out of channel 0's register window
            asm volatile("" ::: "memory");
        }
        return;
    }

    // ===== border path: per-voxel fully predicated, zero padding =====
#pragma unroll
    for (int v = 0; v < VPT; ++v) {
        const float ix = fmaf((float)v, dix, ix0);
        const float iy = fmaf((float)v, diy, iy0);
        const float iz = fmaf((float)v, diz, iz0);
        const float flx = floorf(ix), fly = floorf(iy), flz = floorf(iz);
        const float gfx = ix - flx, gfy = iy - fly, gfz = iz - flz;
        const int x0 = (int)flx, y0 = (int)fly, z0 = (int)flz;

        const bool vx0 = (unsigned)x0       < (unsigned)W;
        const bool vx1 = (unsigned)(x0 + 1) < (unsigned)W;
        const bool vy0 = (unsigned)y0       < (unsigned)H;
        const bool vy1 = (unsigned)(y0 + 1) < (unsigned)H;
        const bool vz0 = (unsigned)z0       < (unsigned)D;
        const bool vz1 = (unsigned)(z0 + 1) < (unsigned)D;

        const bool p000 = vz0 & vy0 & vx0, p001 = vz0 & vy0 & vx1;
        const bool p010 = vz0 & vy1 & vx0, p011 = vz0 & vy1 & vx1;
        const bool p100 = vz1 & vy0 & vx0, p101 = vz1 & vy0 & vx1;
        const bool p110 = vz1 & vy1 & vx0, p111 = vz1 & vy1 & vx1;

        const float* pbase = sb + ((size_t)((z0 * H + y0) * W + x0));

#pragma unroll
        for (int ch = 0; ch < 2; ++ch) {
            const float* p = pbase + (size_t)ch * DHW;

            float l00 = p000 ? __ldg(p)              : 0.0f;
            float l01 = p001 ? __ldg(p + 1)          : 0.0f;
            float l10 = p010 ? __ldg(p + W)          : 0.0f;
            float l11 = p011 ? __ldg(p + W + 1)      : 0.0f;
            float u00 = p100 ? __ldg(p + HW)         : 0.0f;
            float u01 = p101 ? __ldg(p + HW + 1)     : 0.0f;
            float u10 = p110 ? __ldg(p + HW + W)     : 0.0f;
            float u11 = p111 ? __ldg(p + HW + W + 1) : 0.0f;

            out[ob + (size_t)v * HW + (size_t)ch * DHW] =
                tri(l00, l01, l10, l11, u00, u01, u10, u11, gfx, gfy, gfz);
        }
    }
}

extern "C" void kernel_launch(void* const* d_in, const int* in_sizes, int n_in,
                              void* d_out, int out_size)
{
    const float* src = (const float*)d_in[0];
    const float* mat = (const float*)d_in[1];
    float* out = (float*)d_out;

    dim3 block(W, 1, 1);                 // 224 threads = 7 warps
    dim3 grid(1, H, B * (D / VPT));      // (1, 192, 80)
    affine_grid_sample_kernel<<<grid, block>>>(src, mat, out);
}